// round 15
// baseline (speedup 1.0000x reference)
#include <cuda_runtime.h>
#include <cuda_fp16.h>
#include <math.h>

#define N_LABELS 30000
#define HIDDEN   1024
#define BATCH    256
#define N_EDGES  29999

#define BCE_BLOCKS 128                    // CTAs owning 2 batch rows each
#define GRID       148
#define REC_CTAS   (GRID - BCE_BLOCKS)    // 20 CTAs: pack indices, then rec
#define NTHREADS   1024
#define NWARPS     (NTHREADS / 32)
#define SMEM_BYTES (N_LABELS * (int)sizeof(__half2))      // 120000 B

#define G_REC_E    4                                      // edges per granule
#define N_GRAN     ((N_EDGES + G_REC_E - 1) / G_REC_E)    // 7500

// Device globals (no allocation allowed).
__device__ double   g_part[GRID][3];     // bce, rec, prob partials
__device__ unsigned g_ticket    = 0;     // final-combine ticket
__device__ unsigned g_work      = 0;     // rec granule counter
__device__ unsigned g_conv_done = 0;     // packed-index completion counter
__device__ unsigned g_pack[N_EDGES];     // parent | (child<<16)

__device__ __forceinline__ int load_idx(const void* p, bool is32, int i) {
    return is32 ? ((const int*)p)[i] : (int)((const long long*)p)[i];
}

__device__ __forceinline__ float block_reduce_f(float v, float* red) {
    const int lane = threadIdx.x & 31;
    const int wid  = threadIdx.x >> 5;
#pragma unroll
    for (int o = 16; o; o >>= 1) v += __shfl_down_sync(0xffffffffu, v, o);
    if (lane == 0) red[wid] = v;
    __syncthreads();
    float r = 0.f;
    if (wid == 0) {
        r = (lane < NWARPS) ? red[lane] : 0.f;
#pragma unroll
        for (int o = 16; o; o >>= 1) r += __shfl_down_sync(0xffffffffu, r, o);
    }
    return r;  // valid on thread 0
}

// ---------------------------------------------------------------------------
// Single persistent kernel, one wave of 148 CTAs.
//   CTAs [0,128): BCE on 2 batch rows -> interleaved half2 sigmoid cache,
//                 then prob gather (packed idx, 2 LDS.32/edge), then rec pool.
//   CTAs [128,148): pack the edge list (uint16 pair per edge), then rec pool.
//   Rec: warp-granule stealing (4 edges/ticket, ticket prefetched), raw idx.
//   Last CTA combines partials, writes the scalar, resets counters.
// ---------------------------------------------------------------------------
__global__ void __launch_bounds__(NTHREADS, 1)
mega_kernel(const float* __restrict__ logits,
            const float* __restrict__ targets,
            const float* __restrict__ params,
            const void* __restrict__ par_raw,
            const void* __restrict__ chi_raw,
            float* __restrict__ out) {
    extern __shared__ __align__(16) __half2 s_pair[];   // [N_LABELS]
    __shared__ float    s_redf[NWARPS];
    __shared__ int      s_is32;
    __shared__ unsigned s_tick;

    const int tid  = threadIdx.x;
    const int lane = tid & 31;
    const int wid  = tid >> 5;

    // --- dtype detection (per CTA) ---
    if (tid == 0) s_is32 = 0;
    __syncthreads();
    if (tid < 64) {
        long long v = ((const long long*)par_raw)[tid];
        if (v < 0 || v >= (long long)N_LABELS) atomicOr(&s_is32, 1);
    }
    __syncthreads();
    const bool is32 = (s_is32 != 0);

    double p_bce = 0.0, p_pr = 0.0;

    if (blockIdx.x < BCE_BLOCKS) {
        // ---------------- BCE phase: stream rows, fill half2 cache ----------
        const int b = blockIdx.x * 2;
        const float4* __restrict__ l0 = (const float4*)(logits  + (size_t)b * N_LABELS);
        const float4* __restrict__ t0 = (const float4*)(targets + (size_t)b * N_LABELS);
        const float4* __restrict__ l1 = (const float4*)(logits  + (size_t)(b + 1) * N_LABELS);
        const float4* __restrict__ t1 = (const float4*)(targets + (size_t)(b + 1) * N_LABELS);
        uint4* spv = (uint4*)s_pair;       // 4 half2 per thread-iter = 16 B

        float bce = 0.f;
        for (int i = tid; i < N_LABELS / 4; i += NTHREADS) {
            float4 la = l0[i], ta = t0[i];
            float4 lb = l1[i], tb = t1[i];
            const float x0[4] = {la.x, la.y, la.z, la.w};
            const float y0[4] = {ta.x, ta.y, ta.z, ta.w};
            const float x1[4] = {lb.x, lb.y, lb.z, lb.w};
            const float y1[4] = {tb.x, tb.y, tb.z, tb.w};
            __half2 pk[4];
#pragma unroll
            for (int k = 0; k < 4; k++) {
                float xa = x0[k];
                float ea = __expf(-fabsf(xa));
                float ra = __frcp_rn(1.f + ea);
                bce += fmaxf(xa, 0.f) - __logf(ra) - xa * y0[k];
                float sa = (xa >= 0.f) ? ra : (1.f - ra);
                float xb = x1[k];
                float eb = __expf(-fabsf(xb));
                float rb = __frcp_rn(1.f + eb);
                bce += fmaxf(xb, 0.f) - __logf(rb) - xb * y1[k];
                float sb = (xb >= 0.f) ? rb : (1.f - rb);
                pk[k] = __floats2half2_rn(sa, sb);     // (row b, row b+1)
            }
            spv[i] = *(const uint4*)pk;
        }
        __syncthreads();

        // ---------------- wait for packed edge list (long since done) -------
        if (tid == 0) {
            while (*(volatile unsigned*)&g_conv_done < REC_CTAS) __nanosleep(64);
        }
        __syncthreads();
        __threadfence();   // acquire g_pack

        // ---------------- prob gather: 1 packed load + 2 LDS.32 per edge ---
        const __half2 z2 = __float2half2_rn(0.f);
        float pr = 0.f;
        for (int e = tid; e < N_EDGES; e += NTHREADS) {
            unsigned v = g_pack[e];
            __half2 sc = s_pair[v >> 16];        // child  (both rows)
            __half2 sp = s_pair[v & 0xffffu];    // parent (both rows)
            __half2 d  = __hmax2(__hsub2(sc, sp), z2);
            float2 f = __half22float2(d);
            pr += f.x + f.y;
        }

        float tb2 = block_reduce_f(bce, s_redf);
        __syncthreads();
        float tp = block_reduce_f(pr, s_redf);
        p_bce = (double)tb2;
        p_pr  = (double)tp;
        __syncthreads();   // s_redf reused by the rec reduction below
    } else {
        // ---------------- pack the edge list (20 CTAs, ~1.5 edges/thread) --
        const int base = (blockIdx.x - BCE_BLOCKS) * NTHREADS + tid;
        for (int i = base; i < N_EDGES; i += REC_CTAS * NTHREADS) {
            unsigned p = (unsigned)load_idx(par_raw, is32, i);
            unsigned c = (unsigned)load_idx(chi_raw, is32, i);
            g_pack[i] = p | (c << 16);
        }
        __syncthreads();
        if (tid == 0) {
            __threadfence();
            atomicAdd(&g_conv_done, 1u);
        }
    }

    // ---------------- rec role: warp-granule work stealing ----------------
    float rec0 = 0.f, rec1 = 0.f;
    {
        unsigned g = 0xffffffffu;
        if (lane == 0) g = atomicAdd(&g_work, 1u);
        g = __shfl_sync(0xffffffffu, g, 0);
        while (g < N_GRAN) {
            const int b4 = (int)g * G_REC_E;
            int k = b4 + (lane & 3);
            if (k > N_EDGES - 1) k = N_EDGES - 1;
            const int vp = load_idx(par_raw, is32, k);
            const int vq = load_idx(chi_raw, is32, k);
            unsigned gn = 0xffffffffu;
            if (lane == 0) gn = atomicAdd(&g_work, 1u);    // prefetch ticket

#pragma unroll
            for (int i = 0; i < G_REC_E; i++) {
                if (b4 + i >= N_EDGES) break;
                const int p = __shfl_sync(0xffffffffu, vp, i);
                const int q = __shfl_sync(0xffffffffu, vq, i);
                const float4* __restrict__ A = (const float4*)params + p * 256 + lane;
                const float4* __restrict__ B = (const float4*)params + q * 256 + lane;
#pragma unroll
                for (int h = 0; h < 2; h++) {
                    float4 a0 = A[h * 128 +  0], a1 = A[h * 128 + 32];
                    float4 a2 = A[h * 128 + 64], a3 = A[h * 128 + 96];
                    float4 b0 = B[h * 128 +  0], b1 = B[h * 128 + 32];
                    float4 b2 = B[h * 128 + 64], b3 = B[h * 128 + 96];
                    float d;
                    d = a0.x - b0.x; rec0 = fmaf(d, d, rec0);
                    d = a0.y - b0.y; rec1 = fmaf(d, d, rec1);
                    d = a0.z - b0.z; rec0 = fmaf(d, d, rec0);
                    d = a0.w - b0.w; rec1 = fmaf(d, d, rec1);
                    d = a1.x - b1.x; rec0 = fmaf(d, d, rec0);
                    d = a1.y - b1.y; rec1 = fmaf(d, d, rec1);
                    d = a1.z - b1.z; rec0 = fmaf(d, d, rec0);
                    d = a1.w - b1.w; rec1 = fmaf(d, d, rec1);
                    d = a2.x - b2.x; rec0 = fmaf(d, d, rec0);
                    d = a2.y - b2.y; rec1 = fmaf(d, d, rec1);
                    d = a2.z - b2.z; rec0 = fmaf(d, d, rec0);
                    d = a2.w - b2.w; rec1 = fmaf(d, d, rec1);
                    d = a3.x - b3.x; rec0 = fmaf(d, d, rec0);
                    d = a3.y - b3.y; rec1 = fmaf(d, d, rec1);
                    d = a3.z - b3.z; rec0 = fmaf(d, d, rec0);
                    d = a3.w - b3.w; rec1 = fmaf(d, d, rec1);
                }
            }
            g = __shfl_sync(0xffffffffu, gn, 0);
        }
    }

    float tr = block_reduce_f(rec0 + rec1, s_redf);
    double p_rec = (double)tr;

    // ---------------- partials + ticket combine ----------------
    if (tid == 0) {
        g_part[blockIdx.x][0] = p_bce;
        g_part[blockIdx.x][1] = p_rec;
        g_part[blockIdx.x][2] = p_pr;
        __threadfence();
        s_tick = atomicAdd(&g_ticket, 1u);
    }
    __syncthreads();

    if (s_tick == GRID - 1) {
        __shared__ double s_redd[NWARPS];
        double sb = 0.0, sr = 0.0, sp = 0.0;
        for (int i = tid; i < GRID; i += NTHREADS) {
            sb += g_part[i][0];
            sr += g_part[i][1];
            sp += g_part[i][2];
        }
#pragma unroll
        for (int o = 16; o; o >>= 1) {
            sb += __shfl_down_sync(0xffffffffu, sb, o);
            sr += __shfl_down_sync(0xffffffffu, sr, o);
            sp += __shfl_down_sync(0xffffffffu, sp, o);
        }
        if (lane == 0) s_redd[wid] = sb;
        __syncthreads();
        if (wid == 0) {
            double v = (lane < NWARPS) ? s_redd[lane] : 0.0;
#pragma unroll
            for (int o = 16; o; o >>= 1) v += __shfl_down_sync(0xffffffffu, v, o);
            sb = v;
        }
        __syncthreads();
        if (lane == 0) s_redd[wid] = sr;
        __syncthreads();
        if (wid == 0) {
            double v = (lane < NWARPS) ? s_redd[lane] : 0.0;
#pragma unroll
            for (int o = 16; o; o >>= 1) v += __shfl_down_sync(0xffffffffu, v, o);
            sr = v;
        }
        __syncthreads();
        if (lane == 0) s_redd[wid] = sp;
        __syncthreads();
        if (wid == 0) {
            double v = (lane < NWARPS) ? s_redd[lane] : 0.0;
#pragma unroll
            for (int o = 16; o; o >>= 1) v += __shfl_down_sync(0xffffffffu, v, o);
            sp = v;
        }
        if (tid == 0) {
            out[0] = (float)(sb / ((double)BATCH * (double)N_LABELS)
                             + 1e-4 * (0.5 * sr + sp));
            g_work      = 0u;    // reset for next graph replay
            g_ticket    = 0u;
            g_conv_done = 0u;
        }
    }
}

// ---------------------------------------------------------------------------
// Launch. Inputs: logits, targets, params, parent_idx, child_idx. Output: f32.
// ---------------------------------------------------------------------------
extern "C" void kernel_launch(void* const* d_in, const int* in_sizes, int n_in,
                              void* d_out, int out_size) {
    const float* logits  = (const float*)d_in[0];
    const float* targets = (const float*)d_in[1];
    const float* params  = (const float*)d_in[2];
    const void*  par     = d_in[3];
    const void*  chi     = d_in[4];
    float* out = (float*)d_out;
    (void)in_sizes; (void)n_in; (void)out_size;

    cudaFuncSetAttribute(mega_kernel,
                         cudaFuncAttributeMaxDynamicSharedMemorySize, SMEM_BYTES);

    mega_kernel<<<GRID, NTHREADS, SMEM_BYTES>>>(logits, targets, params,
                                                par, chi, out);
}